// round 2
// baseline (speedup 1.0000x reference)
#include <cuda_runtime.h>
#include <math.h>

#define DIM   192
#define HEADS 4
#define HD    48
#define CTX   256
#define HID   510
#define B     8
#define HW    16384   // 128*128
#define W3    576     // 3*DIM
#define FFNC  1020    // 2*HID

// ---------------- scratch (device globals; allocation-free) ----------------
__device__ float g_xn [(long)B*DIM*HW];     // LN output (reused ln1/ln2)
__device__ float g_a  [(long)B*FFNC*HW];    // qkv pre-dw / ffn pre-dw
__device__ float g_b  [(long)B*FFNC*HW];    // qkv post-dw / ffn gated y
__device__ float g_c  [(long)B*DIM*HW];     // out_local + out_global
__device__ float g_d  [(long)B*DIM*HW];     // x after attention block
__device__ float g_ss [B*W3];               // sum of squares per (b, qkv-channel)
__device__ float g_gram[B*HEADS*HD*HD];
__device__ float g_attn[B*HEADS*HD*HD];
__device__ float g_temp[B*HEADS];
__device__ float g_vg  [B*DIM];

// ---------------- init: zero accumulators ----------------
__global__ void zero_kernel() {
    int i = blockIdx.x * 256 + threadIdx.x;
    if (i < B*W3) g_ss[i] = 0.f;
    if (i < B*HEADS*HD*HD) g_gram[i] = 0.f;
}

// ---------------- context MLPs ----------------
__global__ void ctx_kernel(const float* __restrict__ ce,
                           const float* __restrict__ ta_w1, const float* __restrict__ ta_b1,
                           const float* __restrict__ ta_w2, const float* __restrict__ ta_b2,
                           const float* __restrict__ vg_w,  const float* __restrict__ vg_b,
                           const float* __restrict__ base_temp)
{
    int b = blockIdx.x;
    __shared__ float sce[CTX];
    __shared__ float t1[48];
    int tid = threadIdx.x;
    sce[tid] = ce[b*CTX + tid];
    __syncthreads();
    if (tid < 48) {
        float s = ta_b1[tid];
        const float* wr = ta_w1 + tid*CTX;
        for (int k = 0; k < CTX; k++) s += wr[k]*sce[k];
        t1[tid] = fmaxf(s, 0.f);
    }
    __syncthreads();
    if (tid < HEADS) {
        float s = ta_b2[tid];
        const float* wr = ta_w2 + tid*48;
        for (int k = 0; k < 48; k++) s += wr[k]*t1[k];
        float tf = 1.f/(1.f+expf(-s)) * 2.f + 0.5f;
        g_temp[b*HEADS + tid] = base_temp[tid] * tf;
    }
    if (tid < DIM) {
        float s = vg_b[tid];
        const float* wr = vg_w + tid*CTX;
        for (int k = 0; k < CTX; k++) s += wr[k]*sce[k];
        g_vg[b*DIM + tid] = 1.f/(1.f+expf(-s));
    }
}

// ---------------- LayerNorm over channel dim ----------------
__global__ void ln_kernel(const float* __restrict__ x, const float* __restrict__ w,
                          const float* __restrict__ bias, float* __restrict__ out)
{
    long g = (long)blockIdx.x * 256 + threadIdx.x;   // 0..B*HW-1
    int b = (int)(g >> 14);
    int p = (int)(g & (HW-1));
    const float* xp = x + (long)b*DIM*HW + p;
    float sum = 0.f, sq = 0.f;
    #pragma unroll 4
    for (int c = 0; c < DIM; c++) { float v = xp[(long)c*HW]; sum += v; sq += v*v; }
    float mu  = sum * (1.f/DIM);
    float var = sq * (1.f/DIM) - mu*mu;
    float inv = rsqrtf(var + 1e-5f);
    float* op = out + (long)b*DIM*HW + p;
    #pragma unroll 4
    for (int c = 0; c < DIM; c++) {
        float v = xp[(long)c*HW];
        op[(long)c*HW] = (v - mu) * inv * w[c] + bias[c];
    }
}

// ---------------- generic SGEMM: C = A*B (+D) ----------------
// A: M x K row-major (per-z offset z*sA). B: K x N. Batch z = zo*zInner+zi.
#define BM 64
#define BN 128
#define BK 16
__global__ __launch_bounds__(256)
void sgemm_kernel(const float* __restrict__ A, long sA,
                  const float* __restrict__ Bm, long sBo, long sBi,
                  float* __restrict__ C, long sCo, long sCi,
                  const float* __restrict__ D, long sDo, long sDi,
                  int M, int N, int K, int zInner)
{
    int z = blockIdx.z;
    int zo = z / zInner, zi = z - zo*zInner;
    A  += (long)z * sA;
    Bm += (long)zo*sBo + (long)zi*sBi;
    C  += (long)zo*sCo + (long)zi*sCi;
    if (D) D += (long)zo*sDo + (long)zi*sDi;

    __shared__ float As[BK][BM];
    __shared__ float Bs[BK][BN];

    int tid = threadIdx.x;
    int tx = tid & 15;     // N dir
    int ty = tid >> 4;     // M dir
    int rowBase = blockIdx.y * BM;
    int colBase = blockIdx.x * BN;

    float acc[4][8];
    #pragma unroll
    for (int i = 0; i < 4; i++)
        #pragma unroll
        for (int j = 0; j < 8; j++) acc[i][j] = 0.f;

    int nkt = (K + BK - 1) / BK;
    for (int kt = 0; kt < nkt; kt++) {
        int k0 = kt * BK;
        #pragma unroll
        for (int i = 0; i < 4; i++) {              // A tile: 64x16
            int idx = tid + i*256;
            int m  = idx >> 4;
            int kk = idx & 15;
            float v = 0.f;
            int gm = rowBase + m, gk = k0 + kk;
            if (gm < M && gk < K) v = A[(long)gm*K + gk];
            As[kk][m] = v;
        }
        #pragma unroll
        for (int i = 0; i < 8; i++) {              // B tile: 16x128
            int idx = tid + i*256;
            int kk = idx >> 7;
            int n  = idx & 127;
            float v = 0.f;
            int gk = k0 + kk;
            if (gk < K) v = Bm[(long)gk*N + colBase + n];
            Bs[kk][n] = v;
        }
        __syncthreads();
        #pragma unroll
        for (int kk = 0; kk < BK; kk++) {
            float a0 = As[kk][ty     ], a1 = As[kk][ty + 16],
                  a2 = As[kk][ty + 32], a3 = As[kk][ty + 48];
            float bf[8];
            #pragma unroll
            for (int j = 0; j < 8; j++) bf[j] = Bs[kk][tx + j*16];
            #pragma unroll
            for (int j = 0; j < 8; j++) {
                acc[0][j] += a0*bf[j];
                acc[1][j] += a1*bf[j];
                acc[2][j] += a2*bf[j];
                acc[3][j] += a3*bf[j];
            }
        }
        __syncthreads();
    }
    #pragma unroll
    for (int i = 0; i < 4; i++) {
        int gm = rowBase + ty + i*16;
        if (gm >= M) continue;
        long rowOff = (long)gm*N + colBase + tx;
        #pragma unroll
        for (int j = 0; j < 8; j++) {
            float v = acc[i][j];
            if (D) v += D[rowOff + j*16];
            C[rowOff + j*16] = v;
        }
    }
}

// ---------------- depthwise 3x3 (SAME, cross-correlation) ----------------
// blockIdx.x = b*Cout + c; input plane = b*CinTotal + cinOff + c; weight idx = c.
__global__ void dwconv_kernel(const float* __restrict__ in, const float* __restrict__ w,
                              float* __restrict__ out, int Cout, int CinTotal, int cinOff,
                              int doSumsq, int climit)
{
    int bc = blockIdx.x;
    int b = bc / Cout, c = bc - b*Cout;
    const float* ip = in + ((long)b*CinTotal + cinOff + c) * HW;
    const float* wp = w + c*9;
    float wv[9];
    #pragma unroll
    for (int i = 0; i < 9; i++) wv[i] = wp[i];

    int p = blockIdx.y * 256 + threadIdx.x;
    int y = p >> 7, xx = p & 127;
    float s = 0.f;
    #pragma unroll
    for (int ky = 0; ky < 3; ky++) {
        int yy = y + ky - 1;
        if (yy < 0 || yy > 127) continue;
        #pragma unroll
        for (int kx = 0; kx < 3; kx++) {
            int xc = xx + kx - 1;
            if (xc < 0 || xc > 127) continue;
            s += wv[ky*3+kx] * ip[yy*128 + xc];
        }
    }
    out[(long)bc*HW + p] = s;

    if (doSumsq) {
        __shared__ float red[256];
        red[threadIdx.x] = (c < climit) ? s*s : 0.f;
        __syncthreads();
        for (int off = 128; off > 0; off >>= 1) {
            if (threadIdx.x < off) red[threadIdx.x] += red[threadIdx.x + off];
            __syncthreads();
        }
        if (threadIdx.x == 0 && c < climit) atomicAdd(&g_ss[bc], red[0]);
    }
}

// ---------------- FFN depthwise + GELU gate ----------------
__global__ void ffn_dwgate_kernel(const float* __restrict__ in, const float* __restrict__ wdw,
                                  float* __restrict__ out)
{
    int bc = blockIdx.x;                 // b*HID + co
    int b = bc / HID, co = bc - b*HID;
    const float* ip1 = in + ((long)b*FFNC + co      ) * HW;
    const float* ip2 = in + ((long)b*FFNC + HID + co) * HW;
    const float* w1 = wdw + co*9;
    const float* w2 = wdw + (HID + co)*9;
    float wv1[9], wv2[9];
    #pragma unroll
    for (int i = 0; i < 9; i++) { wv1[i] = w1[i]; wv2[i] = w2[i]; }

    int p = blockIdx.y * 256 + threadIdx.x;
    int y = p >> 7, xx = p & 127;
    float h1 = 0.f, h2 = 0.f;
    #pragma unroll
    for (int ky = 0; ky < 3; ky++) {
        int yy = y + ky - 1;
        if (yy < 0 || yy > 127) continue;
        #pragma unroll
        for (int kx = 0; kx < 3; kx++) {
            int xc = xx + kx - 1;
            if (xc < 0 || xc > 127) continue;
            float v1 = ip1[yy*128 + xc];
            float v2 = ip2[yy*128 + xc];
            h1 += wv1[ky*3+kx] * v1;
            h2 += wv2[ky*3+kx] * v2;
        }
    }
    float ge = 0.5f * h1 * (1.f + erff(h1 * 0.70710678118654752f));
    out[((long)b*HID + co)*HW + p] = ge * h2;
}

// ---------------- Gram matrix (split-K, atomic) ----------------
__global__ void gram_kernel(const float* __restrict__ qk)
{
    int bh = blockIdx.x;                 // b*HEADS + h
    int b = bh >> 2, h = bh & 3;
    int nstart = blockIdx.y * 1024;
    const float* qbase = qk + ((long)b*W3 +        h*HD) * HW;
    const float* kbase = qk + ((long)b*W3 + DIM +  h*HD) * HW;
    __shared__ float qs[HD][32], ks[HD][32];
    int tid = threadIdx.x;
    int ti = tid >> 4, tj = tid & 15;    // 16x16; each owns 3x3
    float acc[3][3];
    #pragma unroll
    for (int i = 0; i < 3; i++)
        #pragma unroll
        for (int j = 0; j < 3; j++) acc[i][j] = 0.f;

    for (int n0 = 0; n0 < 1024; n0 += 32) {
        #pragma unroll
        for (int i = 0; i < 6; i++) {
            int idx = tid + i*256;        // 0..1535
            int cc = idx >> 5, nn = idx & 31;
            long off = (long)cc*HW + nstart + n0 + nn;
            qs[cc][nn] = qbase[off];
            ks[cc][nn] = kbase[off];
        }
        __syncthreads();
        #pragma unroll 8
        for (int nn = 0; nn < 32; nn++) {
            float q0 = qs[ti*3+0][nn], q1 = qs[ti*3+1][nn], q2 = qs[ti*3+2][nn];
            float k0 = ks[tj*3+0][nn], k1 = ks[tj*3+1][nn], k2 = ks[tj*3+2][nn];
            acc[0][0] += q0*k0; acc[0][1] += q0*k1; acc[0][2] += q0*k2;
            acc[1][0] += q1*k0; acc[1][1] += q1*k1; acc[1][2] += q1*k2;
            acc[2][0] += q2*k0; acc[2][1] += q2*k1; acc[2][2] += q2*k2;
        }
        __syncthreads();
    }
    #pragma unroll
    for (int i = 0; i < 3; i++)
        #pragma unroll
        for (int j = 0; j < 3; j++)
            atomicAdd(&g_gram[((long)bh*HD + ti*3+i)*HD + tj*3+j], acc[i][j]);
}

// ---------------- softmax with norms, temperature, v_gate fold ----------------
__global__ void softmax_kernel()
{
    int bh = blockIdx.x;
    int b = bh >> 2, h = bh & 3;
    __shared__ float invq[HD], invk[HD], vg[HD];
    int tid = threadIdx.x;  // 64
    if (tid < HD) {
        float nq = sqrtf(g_ss[b*W3 +        h*HD + tid]);
        float nk = sqrtf(g_ss[b*W3 + DIM +  h*HD + tid]);
        invq[tid] = 1.f / fmaxf(nq, 1e-12f);
        invk[tid] = 1.f / fmaxf(nk, 1e-12f);
        vg[tid] = g_vg[b*DIM + h*HD + tid];
    }
    __syncthreads();
    if (tid < HD) {
        float tmp = g_temp[bh];
        const float scale = 0.14433756729740643f;   // 48^-0.5
        float fac = scale * invq[tid] * tmp;
        float row[HD];
        float mx = -1e30f;
        #pragma unroll 8
        for (int j = 0; j < HD; j++) {
            float v = g_gram[((long)bh*HD + tid)*HD + j] * fac * invk[j];
            row[j] = v;
            mx = fmaxf(mx, v);
        }
        float sum = 0.f;
        #pragma unroll 8
        for (int j = 0; j < HD; j++) { row[j] = expf(row[j] - mx); sum += row[j]; }
        float inv = 1.f / sum;
        #pragma unroll 8
        for (int j = 0; j < HD; j++)
            g_attn[((long)bh*HD + tid)*HD + j] = row[j] * inv * vg[j];
    }
}

// ---------------- launch ----------------
extern "C" void kernel_launch(void* const* d_in, const int* in_sizes, int n_in,
                              void* d_out, int out_size)
{
    const float* x        = (const float*)d_in[0];
    const float* ce       = (const float*)d_in[1];
    const float* ln1_w    = (const float*)d_in[2];
    const float* ln1_b    = (const float*)d_in[3];
    const float* ln2_w    = (const float*)d_in[4];
    const float* ln2_b    = (const float*)d_in[5];
    const float* w_qkv    = (const float*)d_in[6];
    const float* w_qkv_dw = (const float*)d_in[7];
    const float* w_proj   = (const float*)d_in[8];
    const float* base_t   = (const float*)d_in[9];
    const float* ta_w1    = (const float*)d_in[10];
    const float* ta_b1    = (const float*)d_in[11];
    const float* ta_w2    = (const float*)d_in[12];
    const float* ta_b2    = (const float*)d_in[13];
    const float* vg_w     = (const float*)d_in[14];
    const float* vg_b     = (const float*)d_in[15];
    const float* w_local  = (const float*)d_in[16];
    const float* w_ffn_in = (const float*)d_in[17];
    const float* w_ffn_dw = (const float*)d_in[18];
    const float* w_ffn_out= (const float*)d_in[19];
    float* out = (float*)d_out;

    float *pxn, *pa, *pb, *pc, *pd;
    cudaGetSymbolAddress((void**)&pxn, g_xn);
    cudaGetSymbolAddress((void**)&pa,  g_a);
    cudaGetSymbolAddress((void**)&pb,  g_b);
    cudaGetSymbolAddress((void**)&pc,  g_c);
    cudaGetSymbolAddress((void**)&pd,  g_d);
    float *pattn;
    cudaGetSymbolAddress((void**)&pattn, g_attn);

    const long PHW = HW;

    zero_kernel<<<288, 256>>>();
    ctx_kernel<<<B, 256>>>(ce, ta_w1, ta_b1, ta_w2, ta_b2, vg_w, vg_b, base_t);

    // LN1
    ln_kernel<<<(B*HW)/256, 256>>>(x, ln1_w, ln1_b, pxn);

    // qkv = W_qkv @ xn   (576 x 16384 per batch)
    sgemm_kernel<<<dim3(HW/BN, (W3+BM-1)/BM, B), 256>>>(
        w_qkv, 0, pxn, DIM*PHW, 0, pa, W3*PHW, 0, nullptr, 0, 0, W3, HW, DIM, 1);

    // depthwise on qkv; accumulate sumsq for q,k (channels < 384)
    dwconv_kernel<<<dim3(B*W3, 64), 256>>>(pa, w_qkv_dw, pb, W3, W3, 0, 1, 2*DIM);

    // Gram
    gram_kernel<<<dim3(B*HEADS, 16), 256>>>(pb);
    softmax_kernel<<<B*HEADS, 64>>>();

    // out_local = dwconv(v, w_local) -> g_c
    dwconv_kernel<<<dim3(B*DIM, 64), 256>>>(pb, w_local, pc, DIM, W3, 2*DIM, 0, 0);

    // out_global = attn' @ v  (+= g_c)
    sgemm_kernel<<<dim3(HW/BN, 1, B*HEADS), 256>>>(
        pattn, HD*HD,
        pb + (long)2*DIM*PHW, W3*PHW, HD*PHW,
        pc, DIM*PHW, HD*PHW,
        pc, DIM*PHW, HD*PHW,
        HD, HW, HD, HEADS);

    // x1 = x + W_proj @ (out_global + out_local)
    sgemm_kernel<<<dim3(HW/BN, DIM/BM, B), 256>>>(
        w_proj, 0, pc, DIM*PHW, 0, pd, DIM*PHW, 0, x, DIM*PHW, 0, DIM, HW, DIM, 1);

    // LN2
    ln_kernel<<<(B*HW)/256, 256>>>(pd, ln2_w, ln2_b, pxn);

    // ffn_in: 1020 x 16384 per batch
    sgemm_kernel<<<dim3(HW/BN, (FFNC+BM-1)/BM, B), 256>>>(
        w_ffn_in, 0, pxn, DIM*PHW, 0, pa, FFNC*PHW, 0, nullptr, 0, 0, FFNC, HW, DIM, 1);

    // depthwise + gelu gate -> 510 channels
    ffn_dwgate_kernel<<<dim3(B*HID, 64), 256>>>(pa, w_ffn_dw, pb);

    // out = x1 + W_ffn_out @ y
    sgemm_kernel<<<dim3(HW/BN, DIM/BM, B), 256>>>(
        w_ffn_out, 0, pb, HID*PHW, 0, out, DIM*PHW, 0, pd, DIM*PHW, 0, DIM, HW, HID, 1);
}

// round 4
// speedup vs baseline: 1.1439x; 1.1439x over previous
#include <cuda_runtime.h>
#include <math.h>

#define DIM   192
#define HEADS 4
#define HD    48
#define CTX   256
#define HID   510
#define B     8
#define HW    16384   // 128*128
#define W3    576     // 3*DIM
#define FFNC  1020    // 2*HID

// ---------------- scratch (device globals; allocation-free) ----------------
__device__ float g_xn [(long)B*DIM*HW];     // LN output (reused ln1/ln2)
__device__ float g_a  [(long)B*FFNC*HW];    // qkv pre-dw / ffn pre-dw
__device__ float g_b  [(long)B*FFNC*HW];    // qkv post-dw / ffn gated y
__device__ float g_c  [(long)B*DIM*HW];     // out_local + out_global
__device__ float g_d  [(long)B*DIM*HW];     // x after attention block
__device__ float g_ss [B*W3];               // sum of squares per (b, qkv-channel)
__device__ float g_gram[B*HEADS*HD*HD];
__device__ float g_attn[B*HEADS*HD*HD];
__device__ float g_temp[B*HEADS];
__device__ float g_vg  [B*DIM];

// ---------------- init: zero accumulators ----------------
__global__ void zero_kernel() {
    int i = blockIdx.x * 256 + threadIdx.x;
    if (i < B*W3) g_ss[i] = 0.f;
    if (i < B*HEADS*HD*HD) g_gram[i] = 0.f;
}

// ---------------- context MLPs ----------------
__global__ void ctx_kernel(const float* __restrict__ ce,
                           const float* __restrict__ ta_w1, const float* __restrict__ ta_b1,
                           const float* __restrict__ ta_w2, const float* __restrict__ ta_b2,
                           const float* __restrict__ vg_w,  const float* __restrict__ vg_b,
                           const float* __restrict__ base_temp)
{
    int b = blockIdx.x;
    __shared__ float sce[CTX];
    __shared__ float t1[48];
    int tid = threadIdx.x;
    sce[tid] = ce[b*CTX + tid];
    __syncthreads();
    if (tid < 48) {
        float s = ta_b1[tid];
        const float* wr = ta_w1 + tid*CTX;
        for (int k = 0; k < CTX; k++) s += wr[k]*sce[k];
        t1[tid] = fmaxf(s, 0.f);
    }
    __syncthreads();
    if (tid < HEADS) {
        float s = ta_b2[tid];
        const float* wr = ta_w2 + tid*48;
        for (int k = 0; k < 48; k++) s += wr[k]*t1[k];
        float tf = 1.f/(1.f+expf(-s)) * 2.f + 0.5f;
        g_temp[b*HEADS + tid] = base_temp[tid] * tf;
    }
    if (tid < DIM) {
        float s = vg_b[tid];
        const float* wr = vg_w + tid*CTX;
        for (int k = 0; k < CTX; k++) s += wr[k]*sce[k];
        g_vg[b*DIM + tid] = 1.f/(1.f+expf(-s));
    }
}

// ---------------- LayerNorm over channel dim ----------------
__global__ void ln_kernel(const float* __restrict__ x, const float* __restrict__ w,
                          const float* __restrict__ bias, float* __restrict__ out)
{
    long g = (long)blockIdx.x * 256 + threadIdx.x;   // 0..B*HW-1
    int b = (int)(g >> 14);
    int p = (int)(g & (HW-1));
    const float* xp = x + (long)b*DIM*HW + p;
    float sum = 0.f, sq = 0.f;
    #pragma unroll 4
    for (int c = 0; c < DIM; c++) { float v = xp[(long)c*HW]; sum += v; sq += v*v; }
    float mu  = sum * (1.f/DIM);
    float var = sq * (1.f/DIM) - mu*mu;
    float inv = rsqrtf(var + 1e-5f);
    float* op = out + (long)b*DIM*HW + p;
    #pragma unroll 4
    for (int c = 0; c < DIM; c++) {
        float v = xp[(long)c*HW];
        op[(long)c*HW] = (v - mu) * inv * w[c] + bias[c];
    }
}

// ---------------- SGEMM: C = A*B (+D), 128x128 tile, 8x8 microtile ----------------
// A: M x K row-major (per-z offset z*sA). B: K x N. Batch z = zo*zInner+zi.
// N and colBase must be multiples of 128 (true for all uses: N = HW).
#define BM 128
#define BN 128
#define BK 16
__global__ __launch_bounds__(256)
void sgemm_kernel(const float* __restrict__ A, long sA,
                  const float* __restrict__ Bm, long sBo, long sBi,
                  float* __restrict__ C, long sCo, long sCi,
                  const float* __restrict__ D, long sDo, long sDi,
                  int M, int N, int K, int zInner)
{
    int z = blockIdx.z;
    int zo = z / zInner, zi = z - zo*zInner;
    A  += (long)z * sA;
    Bm += (long)zo*sBo + (long)zi*sBi;
    C  += (long)zo*sCo + (long)zi*sCi;
    if (D) D += (long)zo*sDo + (long)zi*sDi;

    __shared__ float As[BK][BM];
    __shared__ float Bs[BK][BN];

    int tid = threadIdx.x;
    int tx = tid & 15;     // N dir
    int ty = tid >> 4;     // M dir
    int rowBase = blockIdx.y * BM;
    int colBase = blockIdx.x * BN;

    // global-load indices
    int m_a  = tid >> 1;           // 0..127
    int kk_a = (tid & 1) * 8;      // 0 or 8
    int kk_b = tid >> 4;           // 0..15
    int n_b  = (tid & 15) * 8;     // 0..120

    float acc[8][8];
    #pragma unroll
    for (int i = 0; i < 8; i++)
        #pragma unroll
        for (int j = 0; j < 8; j++) acc[i][j] = 0.f;

    int nkt = (K + BK - 1) / BK;
    for (int kt = 0; kt < nkt; kt++) {
        int k0 = kt * BK;
        // A tile: 128x16 (scalar, K-stride may be unaligned e.g. K=510)
        {
            int gm = rowBase + m_a;
            const float* ap = A + (long)gm*K + k0 + kk_a;
            #pragma unroll
            for (int j = 0; j < 8; j++) {
                int gk = k0 + kk_a + j;
                float v = 0.f;
                if (gm < M && gk < K) v = ap[j];
                As[kk_a + j][m_a] = v;
            }
        }
        // B tile: 16x128 (float4; N row is 16-float aligned)
        {
            int gk = k0 + kk_b;
            float4 v0 = make_float4(0.f,0.f,0.f,0.f), v1 = v0;
            if (gk < K) {
                const float4* bp = (const float4*)(Bm + (long)gk*N + colBase + n_b);
                v0 = bp[0]; v1 = bp[1];
            }
            *(float4*)&Bs[kk_b][n_b]     = v0;
            *(float4*)&Bs[kk_b][n_b + 4] = v1;
        }
        __syncthreads();
        #pragma unroll
        for (int kk = 0; kk < BK; kk++) {
            float4 a0 = *(const float4*)&As[kk][ty*4];
            float4 a1 = *(const float4*)&As[kk][64 + ty*4];
            float4 b0 = *(const float4*)&Bs[kk][tx*4];
            float4 b1 = *(const float4*)&Bs[kk][64 + tx*4];
            float av[8] = {a0.x,a0.y,a0.z,a0.w,a1.x,a1.y,a1.z,a1.w};
            float bv[8] = {b0.x,b0.y,b0.z,b0.w,b1.x,b1.y,b1.z,b1.w};
            #pragma unroll
            for (int i = 0; i < 8; i++)
                #pragma unroll
                for (int j = 0; j < 8; j++)
                    acc[i][j] += av[i]*bv[j];
        }
        __syncthreads();
    }

    // epilogue (float4 loads/stores; cols always in-range since N%128==0)
    #pragma unroll
    for (int i = 0; i < 8; i++) {
        int gm = rowBase + ((i < 4) ? (ty*4 + i) : (64 + ty*4 + (i-4)));
        if (gm >= M) continue;
        long off0 = (long)gm*N + colBase + tx*4;
        long off1 = off0 + 64;
        float4 r0 = make_float4(acc[i][0], acc[i][1], acc[i][2], acc[i][3]);
        float4 r1 = make_float4(acc[i][4], acc[i][5], acc[i][6], acc[i][7]);
        if (D) {
            float4 d0 = *(const float4*)(D + off0);
            float4 d1 = *(const float4*)(D + off1);
            r0.x += d0.x; r0.y += d0.y; r0.z += d0.z; r0.w += d0.w;
            r1.x += d1.x; r1.y += d1.y; r1.z += d1.z; r1.w += d1.w;
        }
        *(float4*)(C + off0) = r0;
        *(float4*)(C + off1) = r1;
    }
}

// ---------------- depthwise 3x3 (SAME, cross-correlation) ----------------
// blockIdx.x = b*Cout + c; input plane = b*CinTotal + cinOff + c; weight idx = c.
__global__ void dwconv_kernel(const float* __restrict__ in, const float* __restrict__ w,
                              float* __restrict__ out, int Cout, int CinTotal, int cinOff,
                              int doSumsq, int climit)
{
    int bc = blockIdx.x;
    int b = bc / Cout, c = bc - b*Cout;
    const float* ip = in + ((long)b*CinTotal + cinOff + c) * HW;
    const float* wp = w + c*9;
    float wv[9];
    #pragma unroll
    for (int i = 0; i < 9; i++) wv[i] = wp[i];

    int p = blockIdx.y * 256 + threadIdx.x;
    int y = p >> 7, xx = p & 127;
    float s = 0.f;
    #pragma unroll
    for (int ky = 0; ky < 3; ky++) {
        int yy = y + ky - 1;
        if (yy < 0 || yy > 127) continue;
        #pragma unroll
        for (int kx = 0; kx < 3; kx++) {
            int xc = xx + kx - 1;
            if (xc < 0 || xc > 127) continue;
            s += wv[ky*3+kx] * ip[yy*128 + xc];
        }
    }
    out[(long)bc*HW + p] = s;

    if (doSumsq) {
        __shared__ float red[256];
        red[threadIdx.x] = (c < climit) ? s*s : 0.f;
        __syncthreads();
        for (int off = 128; off > 0; off >>= 1) {
            if (threadIdx.x < off) red[threadIdx.x] += red[threadIdx.x + off];
            __syncthreads();
        }
        if (threadIdx.x == 0 && c < climit) atomicAdd(&g_ss[bc], red[0]);
    }
}

// ---------------- FFN depthwise + GELU gate ----------------
__global__ void ffn_dwgate_kernel(const float* __restrict__ in, const float* __restrict__ wdw,
                                  float* __restrict__ out)
{
    int bc = blockIdx.x;                 // b*HID + co
    int b = bc / HID, co = bc - b*HID;
    const float* ip1 = in + ((long)b*FFNC + co      ) * HW;
    const float* ip2 = in + ((long)b*FFNC + HID + co) * HW;
    const float* w1 = wdw + co*9;
    const float* w2 = wdw + (HID + co)*9;
    float wv1[9], wv2[9];
    #pragma unroll
    for (int i = 0; i < 9; i++) { wv1[i] = w1[i]; wv2[i] = w2[i]; }

    int p = blockIdx.y * 256 + threadIdx.x;
    int y = p >> 7, xx = p & 127;
    float h1 = 0.f, h2 = 0.f;
    #pragma unroll
    for (int ky = 0; ky < 3; ky++) {
        int yy = y + ky - 1;
        if (yy < 0 || yy > 127) continue;
        #pragma unroll
        for (int kx = 0; kx < 3; kx++) {
            int xc = xx + kx - 1;
            if (xc < 0 || xc > 127) continue;
            float v1 = ip1[yy*128 + xc];
            float v2 = ip2[yy*128 + xc];
            h1 += wv1[ky*3+kx] * v1;
            h2 += wv2[ky*3+kx] * v2;
        }
    }
    float ge = 0.5f * h1 * (1.f + erff(h1 * 0.70710678118654752f));
    out[((long)b*HID + co)*HW + p] = ge * h2;
}

// ---------------- Gram matrix (split-K, atomic) ----------------
__global__ void gram_kernel(const float* __restrict__ qk)
{
    int bh = blockIdx.x;                 // b*HEADS + h
    int b = bh >> 2, h = bh & 3;
    int nstart = blockIdx.y * 1024;
    const float* qbase = qk + ((long)b*W3 +        h*HD) * HW;
    const float* kbase = qk + ((long)b*W3 + DIM +  h*HD) * HW;
    __shared__ float qs[HD][32], ks[HD][32];
    int tid = threadIdx.x;
    int ti = tid >> 4, tj = tid & 15;    // 16x16; each owns 3x3
    float acc[3][3];
    #pragma unroll
    for (int i = 0; i < 3; i++)
        #pragma unroll
        for (int j = 0; j < 3; j++) acc[i][j] = 0.f;

    for (int n0 = 0; n0 < 1024; n0 += 32) {
        #pragma unroll
        for (int i = 0; i < 6; i++) {
            int idx = tid + i*256;        // 0..1535
            int cc = idx >> 5, nn = idx & 31;
            long off = (long)cc*HW + nstart + n0 + nn;
            qs[cc][nn] = qbase[off];
            ks[cc][nn] = kbase[off];
        }
        __syncthreads();
        #pragma unroll 8
        for (int nn = 0; nn < 32; nn++) {
            float q0 = qs[ti*3+0][nn], q1 = qs[ti*3+1][nn], q2 = qs[ti*3+2][nn];
            float k0 = ks[tj*3+0][nn], k1 = ks[tj*3+1][nn], k2 = ks[tj*3+2][nn];
            acc[0][0] += q0*k0; acc[0][1] += q0*k1; acc[0][2] += q0*k2;
            acc[1][0] += q1*k0; acc[1][1] += q1*k1; acc[1][2] += q1*k2;
            acc[2][0] += q2*k0; acc[2][1] += q2*k1; acc[2][2] += q2*k2;
        }
        __syncthreads();
    }
    #pragma unroll
    for (int i = 0; i < 3; i++)
        #pragma unroll
        for (int j = 0; j < 3; j++)
            atomicAdd(&g_gram[((long)bh*HD + ti*3+i)*HD + tj*3+j], acc[i][j]);
}

// ---------------- softmax with norms, temperature, v_gate fold ----------------
__global__ void softmax_kernel()
{
    int bh = blockIdx.x;
    int b = bh >> 2, h = bh & 3;
    __shared__ float invq[HD], invk[HD], vg[HD];
    int tid = threadIdx.x;  // 64
    if (tid < HD) {
        float nq = sqrtf(g_ss[b*W3 +        h*HD + tid]);
        float nk = sqrtf(g_ss[b*W3 + DIM +  h*HD + tid]);
        invq[tid] = 1.f / fmaxf(nq, 1e-12f);
        invk[tid] = 1.f / fmaxf(nk, 1e-12f);
        vg[tid] = g_vg[b*DIM + h*HD + tid];
    }
    __syncthreads();
    if (tid < HD) {
        float tmp = g_temp[bh];
        const float scale = 0.14433756729740643f;   // 48^-0.5
        float fac = scale * invq[tid] * tmp;
        float row[HD];
        float mx = -1e30f;
        #pragma unroll 8
        for (int j = 0; j < HD; j++) {
            float v = g_gram[((long)bh*HD + tid)*HD + j] * fac * invk[j];
            row[j] = v;
            mx = fmaxf(mx, v);
        }
        float sum = 0.f;
        #pragma unroll 8
        for (int j = 0; j < HD; j++) { row[j] = expf(row[j] - mx); sum += row[j]; }
        float inv = 1.f / sum;
        #pragma unroll 8
        for (int j = 0; j < HD; j++)
            g_attn[((long)bh*HD + tid)*HD + j] = row[j] * inv * vg[j];
    }
}

// ---------------- launch ----------------
extern "C" void kernel_launch(void* const* d_in, const int* in_sizes, int n_in,
                              void* d_out, int out_size)
{
    const float* x        = (const float*)d_in[0];
    const float* ce       = (const float*)d_in[1];
    const float* ln1_w    = (const float*)d_in[2];
    const float* ln1_b    = (const float*)d_in[3];
    const float* ln2_w    = (const float*)d_in[4];
    const float* ln2_b    = (const float*)d_in[5];
    const float* w_qkv    = (const float*)d_in[6];
    const float* w_qkv_dw = (const float*)d_in[7];
    const float* w_proj   = (const float*)d_in[8];
    const float* base_t   = (const float*)d_in[9];
    const float* ta_w1    = (const float*)d_in[10];
    const float* ta_b1    = (const float*)d_in[11];
    const float* ta_w2    = (const float*)d_in[12];
    const float* ta_b2    = (const float*)d_in[13];
    const float* vg_w     = (const float*)d_in[14];
    const float* vg_b     = (const float*)d_in[15];
    const float* w_local  = (const float*)d_in[16];
    const float* w_ffn_in = (const float*)d_in[17];
    const float* w_ffn_dw = (const float*)d_in[18];
    const float* w_ffn_out= (const float*)d_in[19];
    float* out = (float*)d_out;

    float *pxn, *pa, *pb, *pc, *pd;
    cudaGetSymbolAddress((void**)&pxn, g_xn);
    cudaGetSymbolAddress((void**)&pa,  g_a);
    cudaGetSymbolAddress((void**)&pb,  g_b);
    cudaGetSymbolAddress((void**)&pc,  g_c);
    cudaGetSymbolAddress((void**)&pd,  g_d);
    float *pattn;
    cudaGetSymbolAddress((void**)&pattn, g_attn);

    const long PHW = HW;

    zero_kernel<<<288, 256>>>();
    ctx_kernel<<<B, 256>>>(ce, ta_w1, ta_b1, ta_w2, ta_b2, vg_w, vg_b, base_t);

    // LN1
    ln_kernel<<<(B*HW)/256, 256>>>(x, ln1_w, ln1_b, pxn);

    // qkv = W_qkv @ xn   (576 x 16384 per batch)
    sgemm_kernel<<<dim3(HW/BN, (W3+BM-1)/BM, B), 256>>>(
        w_qkv, 0, pxn, DIM*PHW, 0, pa, W3*PHW, 0, nullptr, 0, 0, W3, HW, DIM, 1);

    // depthwise on qkv; accumulate sumsq for q,k (channels < 384)
    dwconv_kernel<<<dim3(B*W3, 64), 256>>>(pa, w_qkv_dw, pb, W3, W3, 0, 1, 2*DIM);

    // Gram
    gram_kernel<<<dim3(B*HEADS, 16), 256>>>(pb);
    softmax_kernel<<<B*HEADS, 64>>>();

    // out_local = dwconv(v, w_local) -> g_c
    dwconv_kernel<<<dim3(B*DIM, 64), 256>>>(pb, w_local, pc, DIM, W3, 2*DIM, 0, 0);

    // out_global = attn' @ v  (+= g_c)
    sgemm_kernel<<<dim3(HW/BN, 1, B*HEADS), 256>>>(
        pattn, HD*HD,
        pb + (long)2*DIM*PHW, W3*PHW, HD*PHW,
        pc, DIM*PHW, HD*PHW,
        pc, DIM*PHW, HD*PHW,
        HD, HW, HD, HEADS);

    // x1 = x + W_proj @ (out_global + out_local)
    sgemm_kernel<<<dim3(HW/BN, (DIM+BM-1)/BM, B), 256>>>(
        w_proj, 0, pc, DIM*PHW, 0, pd, DIM*PHW, 0, x, DIM*PHW, 0, DIM, HW, DIM, 1);

    // LN2
    ln_kernel<<<(B*HW)/256, 256>>>(pd, ln2_w, ln2_b, pxn);

    // ffn_in: 1020 x 16384 per batch
    sgemm_kernel<<<dim3(HW/BN, (FFNC+BM-1)/BM, B), 256>>>(
        w_ffn_in, 0, pxn, DIM*PHW, 0, pa, FFNC*PHW, 0, nullptr, 0, 0, FFNC, HW, DIM, 1);

    // depthwise + gelu gate -> 510 channels
    ffn_dwgate_kernel<<<dim3(B*HID, 64), 256>>>(pa, w_ffn_dw, pb);

    // out = x1 + W_ffn_out @ y
    sgemm_kernel<<<dim3(HW/BN, (DIM+BM-1)/BM, B), 256>>>(
        w_ffn_out, 0, pb, HID*PHW, 0, out, DIM*PHW, 0, pd, DIM*PHW, 0, DIM, HW, HID, 1);
}

// round 6
// speedup vs baseline: 1.6260x; 1.4215x over previous
#include <cuda_runtime.h>
#include <math.h>

#define DIM   192
#define HEADS 4
#define HD    48
#define CTX   256
#define HID   510
#define B     8
#define HW    16384   // 128*128
#define W3    576     // 3*DIM
#define FFNC  1020    // 2*HID

// ---------------- scratch (device globals; allocation-free) ----------------
__device__ float g_xn [(long)B*DIM*HW];     // LN output (reused ln1/ln2)
__device__ float g_a  [(long)B*FFNC*HW];    // qkv pre-dw / ffn pre-dw
__device__ float g_b  [(long)B*FFNC*HW];    // qkv post-dw / ffn gated y
__device__ float g_c  [(long)B*DIM*HW];     // out_local + out_global
__device__ float g_d  [(long)B*DIM*HW];     // x after attention block
__device__ float g_ss [B*W3];               // sum of squares per (b, qkv-channel)
__device__ float g_gram[B*HEADS*HD*HD];
__device__ float g_attn[B*HEADS*HD*HD];
__device__ float g_temp[B*HEADS];
__device__ float g_vg  [B*DIM];

// ---------------- init: zero accumulators ----------------
__global__ void zero_kernel() {
    int i = blockIdx.x * 256 + threadIdx.x;
    if (i < B*W3) g_ss[i] = 0.f;
    if (i < B*HEADS*HD*HD) g_gram[i] = 0.f;
}

// ---------------- context MLPs ----------------
__global__ void ctx_kernel(const float* __restrict__ ce,
                           const float* __restrict__ ta_w1, const float* __restrict__ ta_b1,
                           const float* __restrict__ ta_w2, const float* __restrict__ ta_b2,
                           const float* __restrict__ vg_w,  const float* __restrict__ vg_b,
                           const float* __restrict__ base_temp)
{
    int b = blockIdx.x;
    __shared__ float sce[CTX];
    __shared__ float t1[48];
    int tid = threadIdx.x;
    sce[tid] = ce[b*CTX + tid];
    __syncthreads();
    if (tid < 48) {
        float s = ta_b1[tid];
        const float* wr = ta_w1 + tid*CTX;
        for (int k = 0; k < CTX; k++) s += wr[k]*sce[k];
        t1[tid] = fmaxf(s, 0.f);
    }
    __syncthreads();
    if (tid < HEADS) {
        float s = ta_b2[tid];
        const float* wr = ta_w2 + tid*48;
        for (int k = 0; k < 48; k++) s += wr[k]*t1[k];
        float tf = 1.f/(1.f+expf(-s)) * 2.f + 0.5f;
        g_temp[b*HEADS + tid] = base_temp[tid] * tf;
    }
    if (tid < DIM) {
        float s = vg_b[tid];
        const float* wr = vg_w + tid*CTX;
        for (int k = 0; k < CTX; k++) s += wr[k]*sce[k];
        g_vg[b*DIM + tid] = 1.f/(1.f+expf(-s));
    }
}

// ---------------- LayerNorm over channel dim ----------------
__global__ void ln_kernel(const float* __restrict__ x, const float* __restrict__ w,
                          const float* __restrict__ bias, float* __restrict__ out)
{
    long g = (long)blockIdx.x * 256 + threadIdx.x;   // 0..B*HW-1
    int b = (int)(g >> 14);
    int p = (int)(g & (HW-1));
    const float* xp = x + (long)b*DIM*HW + p;
    float sum = 0.f, sq = 0.f;
    #pragma unroll 4
    for (int c = 0; c < DIM; c++) { float v = xp[(long)c*HW]; sum += v; sq += v*v; }
    float mu  = sum * (1.f/DIM);
    float var = sq * (1.f/DIM) - mu*mu;
    float inv = rsqrtf(var + 1e-5f);
    float* op = out + (long)b*DIM*HW + p;
    #pragma unroll 4
    for (int c = 0; c < DIM; c++) {
        float v = xp[(long)c*HW];
        op[(long)c*HW] = (v - mu) * inv * w[c] + bias[c];
    }
}

// ---------------- TF32 tensor-core GEMM: C = A*B (+D) ----------------
// A: M x K row-major (per-z offset z*sA). B: K x N. Batch z = zo*zInner+zi.
// N and colBase multiples of 128 (true: N = HW). fp32 accumulate.
#define BM 128
#define BN 128
#define BKT 32
#define APAD 36     // stride%32 == 4 -> bank(4g+t) bijective over warp
#define BPAD 136    // stride%32 == 8 -> bank(8t+g) bijective over warp

__device__ __forceinline__ unsigned f2tf32(float f) {
    unsigned r;
    asm("cvt.rna.tf32.f32 %0, %1;" : "=r"(r) : "f"(f));
    return r;
}
__device__ __forceinline__ void mma_tf32(float* d, const unsigned* a, const unsigned* b) {
    asm volatile(
        "mma.sync.aligned.m16n8k8.row.col.f32.tf32.tf32.f32 "
        "{%0,%1,%2,%3}, {%4,%5,%6,%7}, {%8,%9}, {%0,%1,%2,%3};"
        : "+f"(d[0]), "+f"(d[1]), "+f"(d[2]), "+f"(d[3])
        : "r"(a[0]), "r"(a[1]), "r"(a[2]), "r"(a[3]), "r"(b[0]), "r"(b[1]));
}

__global__ __launch_bounds__(256)
void sgemm_kernel(const float* __restrict__ A, long sA,
                  const float* __restrict__ Bm, long sBo, long sBi,
                  float* __restrict__ C, long sCo, long sCi,
                  const float* __restrict__ D, long sDo, long sDi,
                  int M, int N, int K, int zInner)
{
    int z = blockIdx.z;
    int zo = z / zInner, zi = z - zo*zInner;
    A  += (long)z * sA;
    Bm += (long)zo*sBo + (long)zi*sBi;
    C  += (long)zo*sCo + (long)zi*sCi;
    if (D) D += (long)zo*sDo + (long)zi*sDi;

    __shared__ unsigned As[BM][APAD];
    __shared__ unsigned Bs[BKT][BPAD];

    int tid  = threadIdx.x;
    int lane = tid & 31;
    int warp = tid >> 5;
    int warpM = warp >> 2;      // 0..1  (64 rows each)
    int warpN = warp & 3;       // 0..3  (32 cols each)
    int g = lane >> 2;          // 0..7
    int t = lane & 3;           // 0..3

    int rowBase = blockIdx.y * BM;
    int colBase = blockIdx.x * BN;

    // loaders
    int m_a  = tid >> 1;            // 0..127
    int ks_a = (tid & 1) * 16;      // 0 or 16
    int row_b = tid >> 3;           // 0..31
    int cs_b  = (tid & 7) * 4;      // 0..28 (each thread: 4 float4 strided by 32)

    float acc[4][4][4];
    #pragma unroll
    for (int i = 0; i < 4; i++)
        #pragma unroll
        for (int j = 0; j < 4; j++)
            #pragma unroll
            for (int r = 0; r < 4; r++) acc[i][j][r] = 0.f;

    int nkt = (K + BKT - 1) / BKT;
    for (int kt = 0; kt < nkt; kt++) {
        int k0 = kt * BKT;
        // ---- A tile: 128 x 32 (scalar; weights are small / L2-resident) ----
        {
            int gm = rowBase + m_a;
            if (gm < M) {
                const float* ap = A + (long)gm*K + k0 + ks_a;
                #pragma unroll
                for (int j = 0; j < 16; j++) {
                    int gk = k0 + ks_a + j;
                    float v = (gk < K) ? ap[j] : 0.f;
                    As[m_a][ks_a + j] = f2tf32(v);
                }
            } else {
                #pragma unroll
                for (int j = 0; j < 16; j++) As[m_a][ks_a + j] = 0u;
            }
        }
        // ---- B tile: 32 x 128 (float4, conflict-free STS layout) ----
        {
            int gk = k0 + row_b;
            if (gk < K) {
                const float* bp = Bm + (long)gk*N + colBase;
                #pragma unroll
                for (int q = 0; q < 4; q++) {
                    float4 v = *(const float4*)(bp + cs_b + q*32);
                    Bs[row_b][cs_b + q*32 + 0] = f2tf32(v.x);
                    Bs[row_b][cs_b + q*32 + 1] = f2tf32(v.y);
                    Bs[row_b][cs_b + q*32 + 2] = f2tf32(v.z);
                    Bs[row_b][cs_b + q*32 + 3] = f2tf32(v.w);
                }
            } else {
                #pragma unroll
                for (int q = 0; q < 4; q++) {
                    Bs[row_b][cs_b + q*32 + 0] = 0u;
                    Bs[row_b][cs_b + q*32 + 1] = 0u;
                    Bs[row_b][cs_b + q*32 + 2] = 0u;
                    Bs[row_b][cs_b + q*32 + 3] = 0u;
                }
            }
        }
        __syncthreads();

        #pragma unroll
        for (int kk = 0; kk < BKT; kk += 8) {
            unsigned af[4][4], bf[4][2];
            #pragma unroll
            for (int i = 0; i < 4; i++) {
                int r = warpM*64 + i*16 + g;
                af[i][0] = As[r    ][kk + t];
                af[i][1] = As[r + 8][kk + t];
                af[i][2] = As[r    ][kk + t + 4];
                af[i][3] = As[r + 8][kk + t + 4];
            }
            #pragma unroll
            for (int j = 0; j < 4; j++) {
                int c = warpN*32 + j*8 + g;
                bf[j][0] = Bs[kk + t    ][c];
                bf[j][1] = Bs[kk + t + 4][c];
            }
            #pragma unroll
            for (int i = 0; i < 4; i++)
                #pragma unroll
                for (int j = 0; j < 4; j++)
                    mma_tf32(acc[i][j], af[i], bf[j]);
        }
        __syncthreads();
    }

    // ---- epilogue: each (i,j) frag -> rows r0,r0+8; cols c..c+1 (float2) ----
    #pragma unroll
    for (int i = 0; i < 4; i++) {
        int r0 = rowBase + warpM*64 + i*16 + g;
        int r1 = r0 + 8;
        #pragma unroll
        for (int j = 0; j < 4; j++) {
            long c = colBase + warpN*32 + j*8 + t*2;
            if (r0 < M) {
                long off = (long)r0*N + c;
                float2 v = make_float2(acc[i][j][0], acc[i][j][1]);
                if (D) { float2 d0 = *(const float2*)(D + off); v.x += d0.x; v.y += d0.y; }
                *(float2*)(C + off) = v;
            }
            if (r1 < M) {
                long off = (long)r1*N + c;
                float2 v = make_float2(acc[i][j][2], acc[i][j][3]);
                if (D) { float2 d1 = *(const float2*)(D + off); v.x += d1.x; v.y += d1.y; }
                *(float2*)(C + off) = v;
            }
        }
    }
}

// ---------------- depthwise 3x3 (SAME, cross-correlation) ----------------
__global__ void dwconv_kernel(const float* __restrict__ in, const float* __restrict__ w,
                              float* __restrict__ out, int Cout, int CinTotal, int cinOff,
                              int doSumsq, int climit)
{
    int bc = blockIdx.x;
    int b = bc / Cout, c = bc - b*Cout;
    const float* ip = in + ((long)b*CinTotal + cinOff + c) * HW;
    const float* wp = w + c*9;
    float wv[9];
    #pragma unroll
    for (int i = 0; i < 9; i++) wv[i] = wp[i];

    int p = blockIdx.y * 256 + threadIdx.x;
    int y = p >> 7, xx = p & 127;
    float s = 0.f;
    #pragma unroll
    for (int ky = 0; ky < 3; ky++) {
        int yy = y + ky - 1;
        if (yy < 0 || yy > 127) continue;
        #pragma unroll
        for (int kx = 0; kx < 3; kx++) {
            int xc = xx + kx - 1;
            if (xc < 0 || xc > 127) continue;
            s += wv[ky*3+kx] * ip[yy*128 + xc];
        }
    }
    out[(long)bc*HW + p] = s;

    if (doSumsq) {
        __shared__ float red[256];
        red[threadIdx.x] = (c < climit) ? s*s : 0.f;
        __syncthreads();
        for (int off = 128; off > 0; off >>= 1) {
            if (threadIdx.x < off) red[threadIdx.x] += red[threadIdx.x + off];
            __syncthreads();
        }
        if (threadIdx.x == 0 && c < climit) atomicAdd(&g_ss[bc], red[0]);
    }
}

// ---------------- FFN depthwise + GELU gate ----------------
__global__ void ffn_dwgate_kernel(const float* __restrict__ in, const float* __restrict__ wdw,
                                  float* __restrict__ out)
{
    int bc = blockIdx.x;                 // b*HID + co
    int b = bc / HID, co = bc - b*HID;
    const float* ip1 = in + ((long)b*FFNC + co      ) * HW;
    const float* ip2 = in + ((long)b*FFNC + HID + co) * HW;
    const float* w1 = wdw + co*9;
    const float* w2 = wdw + (HID + co)*9;
    float wv1[9], wv2[9];
    #pragma unroll
    for (int i = 0; i < 9; i++) { wv1[i] = w1[i]; wv2[i] = w2[i]; }

    int p = blockIdx.y * 256 + threadIdx.x;
    int y = p >> 7, xx = p & 127;
    float h1 = 0.f, h2 = 0.f;
    #pragma unroll
    for (int ky = 0; ky < 3; ky++) {
        int yy = y + ky - 1;
        if (yy < 0 || yy > 127) continue;
        #pragma unroll
        for (int kx = 0; kx < 3; kx++) {
            int xc = xx + kx - 1;
            if (xc < 0 || xc > 127) continue;
            float v1 = ip1[yy*128 + xc];
            float v2 = ip2[yy*128 + xc];
            h1 += wv1[ky*3+kx] * v1;
            h2 += wv2[ky*3+kx] * v2;
        }
    }
    float ge = 0.5f * h1 * (1.f + erff(h1 * 0.70710678118654752f));
    out[((long)b*HID + co)*HW + p] = ge * h2;
}

// ---------------- Gram matrix (split-K, atomic) ----------------
__global__ void gram_kernel(const float* __restrict__ qk)
{
    int bh = blockIdx.x;                 // b*HEADS + h
    int b = bh >> 2, h = bh & 3;
    int nstart = blockIdx.y * 1024;
    const float* qbase = qk + ((long)b*W3 +        h*HD) * HW;
    const float* kbase = qk + ((long)b*W3 + DIM +  h*HD) * HW;
    __shared__ float qs[HD][32], ks[HD][32];
    int tid = threadIdx.x;
    int ti = tid >> 4, tj = tid & 15;    // 16x16; each owns 3x3
    float acc[3][3];
    #pragma unroll
    for (int i = 0; i < 3; i++)
        #pragma unroll
        for (int j = 0; j < 3; j++) acc[i][j] = 0.f;

    for (int n0 = 0; n0 < 1024; n0 += 32) {
        #pragma unroll
        for (int i = 0; i < 6; i++) {
            int idx = tid + i*256;        // 0..1535
            int cc = idx >> 5, nn = idx & 31;
            long off = (long)cc*HW + nstart + n0 + nn;
            qs[cc][nn] = qbase[off];
            ks[cc][nn] = kbase[off];
        }
        __syncthreads();
        #pragma unroll 8
        for (int nn = 0; nn < 32; nn++) {
            float q0 = qs[ti*3+0][nn], q1 = qs[ti*3+1][nn], q2 = qs[ti*3+2][nn];
            float k0 = ks[tj*3+0][nn], k1 = ks[tj*3+1][nn], k2 = ks[tj*3+2][nn];
            acc[0][0] += q0*k0; acc[0][1] += q0*k1; acc[0][2] += q0*k2;
            acc[1][0] += q1*k0; acc[1][1] += q1*k1; acc[1][2] += q1*k2;
            acc[2][0] += q2*k0; acc[2][1] += q2*k1; acc[2][2] += q2*k2;
        }
        __syncthreads();
    }
    #pragma unroll
    for (int i = 0; i < 3; i++)
        #pragma unroll
        for (int j = 0; j < 3; j++)
            atomicAdd(&g_gram[((long)bh*HD + ti*3+i)*HD + tj*3+j], acc[i][j]);
}

// ---------------- softmax with norms, temperature, v_gate fold ----------------
__global__ void softmax_kernel()
{
    int bh = blockIdx.x;
    int b = bh >> 2, h = bh & 3;
    __shared__ float invq[HD], invk[HD], vg[HD];
    int tid = threadIdx.x;  // 64
    if (tid < HD) {
        float nq = sqrtf(g_ss[b*W3 +        h*HD + tid]);
        float nk = sqrtf(g_ss[b*W3 + DIM +  h*HD + tid]);
        invq[tid] = 1.f / fmaxf(nq, 1e-12f);
        invk[tid] = 1.f / fmaxf(nk, 1e-12f);
        vg[tid] = g_vg[b*DIM + h*HD + tid];
    }
    __syncthreads();
    if (tid < HD) {
        float tmp = g_temp[bh];
        const float scale = 0.14433756729740643f;   // 48^-0.5
        float fac = scale * invq[tid] * tmp;
        float row[HD];
        float mx = -1e30f;
        #pragma unroll 8
        for (int j = 0; j < HD; j++) {
            float v = g_gram[((long)bh*HD + tid)*HD + j] * fac * invk[j];
            row[j] = v;
            mx = fmaxf(mx, v);
        }
        float sum = 0.f;
        #pragma unroll 8
        for (int j = 0; j < HD; j++) { row[j] = expf(row[j] - mx); sum += row[j]; }
        float inv = 1.f / sum;
        #pragma unroll 8
        for (int j = 0; j < HD; j++)
            g_attn[((long)bh*HD + tid)*HD + j] = row[j] * inv * vg[j];
    }
}

// ---------------- launch ----------------
extern "C" void kernel_launch(void* const* d_in, const int* in_sizes, int n_in,
                              void* d_out, int out_size)
{
    const float* x        = (const float*)d_in[0];
    const float* ce       = (const float*)d_in[1];
    const float* ln1_w    = (const float*)d_in[2];
    const float* ln1_b    = (const float*)d_in[3];
    const float* ln2_w    = (const float*)d_in[4];
    const float* ln2_b    = (const float*)d_in[5];
    const float* w_qkv    = (const float*)d_in[6];
    const float* w_qkv_dw = (const float*)d_in[7];
    const float* w_proj   = (const float*)d_in[8];
    const float* base_t   = (const float*)d_in[9];
    const float* ta_w1    = (const float*)d_in[10];
    const float* ta_b1    = (const float*)d_in[11];
    const float* ta_w2    = (const float*)d_in[12];
    const float* ta_b2    = (const float*)d_in[13];
    const float* vg_w     = (const float*)d_in[14];
    const float* vg_b     = (const float*)d_in[15];
    const float* w_local  = (const float*)d_in[16];
    const float* w_ffn_in = (const float*)d_in[17];
    const float* w_ffn_dw = (const float*)d_in[18];
    const float* w_ffn_out= (const float*)d_in[19];
    float* out = (float*)d_out;

    float *pxn, *pa, *pb, *pc, *pd;
    cudaGetSymbolAddress((void**)&pxn, g_xn);
    cudaGetSymbolAddress((void**)&pa,  g_a);
    cudaGetSymbolAddress((void**)&pb,  g_b);
    cudaGetSymbolAddress((void**)&pc,  g_c);
    cudaGetSymbolAddress((void**)&pd,  g_d);
    float *pattn;
    cudaGetSymbolAddress((void**)&pattn, g_attn);

    const long PHW = HW;

    zero_kernel<<<288, 256>>>();
    ctx_kernel<<<B, 256>>>(ce, ta_w1, ta_b1, ta_w2, ta_b2, vg_w, vg_b, base_t);

    // LN1
    ln_kernel<<<(B*HW)/256, 256>>>(x, ln1_w, ln1_b, pxn);

    // qkv = W_qkv @ xn   (576 x 16384 per batch)
    sgemm_kernel<<<dim3(HW/BN, (W3+BM-1)/BM, B), 256>>>(
        w_qkv, 0, pxn, DIM*PHW, 0, pa, W3*PHW, 0, nullptr, 0, 0, W3, HW, DIM, 1);

    // depthwise on qkv; accumulate sumsq for q,k (channels < 384)
    dwconv_kernel<<<dim3(B*W3, 64), 256>>>(pa, w_qkv_dw, pb, W3, W3, 0, 1, 2*DIM);

    // Gram
    gram_kernel<<<dim3(B*HEADS, 16), 256>>>(pb);
    softmax_kernel<<<B*HEADS, 64>>>();

    // out_local = dwconv(v, w_local) -> g_c
    dwconv_kernel<<<dim3(B*DIM, 64), 256>>>(pb, w_local, pc, DIM, W3, 2*DIM, 0, 0);

    // out_global = attn' @ v  (+= g_c)
    sgemm_kernel<<<dim3(HW/BN, 1, B*HEADS), 256>>>(
        pattn, HD*HD,
        pb + (long)2*DIM*PHW, W3*PHW, HD*PHW,
        pc, DIM*PHW, HD*PHW,
        pc, DIM*PHW, HD*PHW,
        HD, HW, HD, HEADS);

    // x1 = x + W_proj @ (out_global + out_local)
    sgemm_kernel<<<dim3(HW/BN, (DIM+BM-1)/BM, B), 256>>>(
        w_proj, 0, pc, DIM*PHW, 0, pd, DIM*PHW, 0, x, DIM*PHW, 0, DIM, HW, DIM, 1);

    // LN2
    ln_kernel<<<(B*HW)/256, 256>>>(pd, ln2_w, ln2_b, pxn);

    // ffn_in: 1020 x 16384 per batch
    sgemm_kernel<<<dim3(HW/BN, (FFNC+BM-1)/BM, B), 256>>>(
        w_ffn_in, 0, pxn, DIM*PHW, 0, pa, FFNC*PHW, 0, nullptr, 0, 0, FFNC, HW, DIM, 1);

    // depthwise + gelu gate -> 510 channels
    ffn_dwgate_kernel<<<dim3(B*HID, 64), 256>>>(pa, w_ffn_dw, pb);

    // out = x1 + W_ffn_out @ y
    sgemm_kernel<<<dim3(HW/BN, (DIM+BM-1)/BM, B), 256>>>(
        w_ffn_out, 0, pb, HID*PHW, 0, out, DIM*PHW, 0, pd, DIM*PHW, 0, DIM, HW, HID, 1);
}